// round 15
// baseline (speedup 1.0000x reference)
#include <cuda_runtime.h>
#include <cuda_fp16.h>
#include <cuda_bf16.h>
#include <cstdint>

#define NN 100000
#define NN_PAD 100096
#define EE 1600000
#define NEDGE (EE + NN)
#define HH 128
#define GG 64
#define OUTD 32

// ---------------- scratch (device globals; zero at module load) ----------------
// Self-cleaning per run: deg (k_pool), gcnt (k_scan blk0), pool (k_mlp),
// cursor (k_prep), aggflag (k_fill). Aimg pad rows: never written, stay zero.
__device__ int    g_deg[NN];
__device__ float  g_dinv[NN];
__device__ int    g_rowoff[NN + 1];
__device__ int    g_cursor[NN];
__device__ int2   g_cw[NEDGE];                    // packed (col, w bits)
__device__ float  g_bufB[(size_t)NN * HH];        // layer-3 GEMM output (pool input)
__device__ unsigned g_feat[(size_t)NN * 64];      // bf16x2 features for gather
__device__ uint2  g_Aimg[(size_t)NN_PAD * 32];    // agg out: fp16 fragment-permuted cells
__device__ uint4  g_Wiv[3 * 2560];                // W^T fp16 paired-kk cells, [128][20]
__device__ float  g_pool[GG * HH];
__device__ int    g_gcnt[GG];
__device__ int    g_goff[GG + 1];
__device__ volatile int g_aggval[128];
__device__ volatile int g_aggflag[128];

// ---------------- fused prep: g_feat = bf16(x) + counts + W images -------------
__global__ void k_prep(const float* __restrict__ x, const int* __restrict__ ei,
                       const int* __restrict__ batch,
                       const float* __restrict__ W1, const float* __restrict__ W2,
                       const float* __restrict__ W3) {
    int idx = blockIdx.x * blockDim.x + threadIdx.x;
    if (idx < NN * 32) {
        int row = idx >> 5, c = idx & 31;
        const float4* xr4 = (const float4*)(x + (size_t)row * 128);
        float4 v = xr4[c];
        __nv_bfloat162 h0 = __floats2bfloat162_rn(v.x, v.y);
        __nv_bfloat162 h1 = __floats2bfloat162_rn(v.z, v.w);
        ((uint2*)g_feat)[(size_t)row * 32 + c] = make_uint2(*(unsigned*)&h0, *(unsigned*)&h1);
        if (idx < NN) { g_cursor[idx] = 0; atomicAdd(&g_gcnt[batch[idx]], 1); }
        if (idx < EE) atomicAdd(&g_deg[ei[EE + idx]], 1);
    } else {
        int r = idx - NN * 32;
        if (r < 3 * 2048) {
            int l = r >> 11, rr = r & 2047;
            const float* W = (l == 0) ? W1 : (l == 1) ? W2 : W3;
            int n = rr >> 4, c = rr & 15;
            int j = c >> 2, q = c & 3;
            int ka = 32 * j + 2 * q;
            int kb = ka + 16;
            __half2 x0 = __floats2half2_rn(W[(size_t)ka * 128 + n],       W[(size_t)(ka + 1) * 128 + n]);
            __half2 y0 = __floats2half2_rn(W[(size_t)(ka + 8) * 128 + n], W[(size_t)(ka + 9) * 128 + n]);
            __half2 z0 = __floats2half2_rn(W[(size_t)kb * 128 + n],       W[(size_t)(kb + 1) * 128 + n]);
            __half2 w0 = __floats2half2_rn(W[(size_t)(kb + 8) * 128 + n], W[(size_t)(kb + 9) * 128 + n]);
            uint4 cell;
            cell.x = *(unsigned*)&x0; cell.y = *(unsigned*)&y0;
            cell.z = *(unsigned*)&z0; cell.w = *(unsigned*)&w0;
            g_Wiv[l * 2560 + n * 20 + c] = cell;
        }
    }
}

// ---------------- single-kernel scan (decoupled lookback, 98 blocks) -----------
#define SCAN_CHUNK 1024
#define SCAN_PARTS ((NN + SCAN_CHUNK - 1) / SCAN_CHUNK)

__global__ void k_scan() {
    __shared__ int s[SCAN_CHUNK];
    __shared__ int sbase;
    int t = threadIdx.x;
    int bid = blockIdx.x;
    int i = bid * SCAN_CHUNK + t;
    int v = 0;
    if (i < NN) {
        v = g_deg[i] + 1;
        g_dinv[i] = rsqrtf((float)v);
    }
    s[t] = v; __syncthreads();
    for (int off = 1; off < SCAN_CHUNK; off <<= 1) {
        int x = (t >= off) ? s[t - off] : 0;
        __syncthreads();
        s[t] += x;
        __syncthreads();
    }
    if (t == 0) {
        sbase = 0;
        g_aggval[bid] = s[SCAN_CHUNK - 1];
        __threadfence();
        g_aggflag[bid] = 1;
        if (bid == 0) {
            int g = 0;
            for (int qq = 0; qq < GG; qq++) {
                g_goff[qq] = g;
                g += g_gcnt[qq];
                g_gcnt[qq] = 0;            // self-clean for next run
            }
            g_goff[GG] = g;
            g_rowoff[NN] = NEDGE;
        }
    }
    __syncthreads();
    if (t < bid) {
        while (g_aggflag[t] == 0) { __nanosleep(64); }
        atomicAdd_block(&sbase, g_aggval[t]);
    }
    __syncthreads();
    if (i < NN) g_rowoff[i] = sbase + s[t] - v;
}

__global__ void k_fill(const int* __restrict__ ei) {
    int idx = blockIdx.x * blockDim.x + threadIdx.x;
    if (idx < 128) g_aggflag[idx] = 0;     // self-clean for next run
    if (idx >= NEDGE) return;
    int s, d;
    if (idx < EE) { s = ei[idx]; d = ei[EE + idx]; }
    else          { s = d = idx - EE; }
    int pos = g_rowoff[d] + atomicAdd(&g_cursor[d], 1);
    float w = g_dinv[s] * g_dinv[d];
    g_cw[pos] = make_int2(s, __float_as_int(w));
}

// ---------------- CSR aggregation (bf16 gather, ALU-expand): Aimg --------------
// warp per dst row; half-warp owns the 256B bf16 row (uint4/lane),
// two edges per warp instruction. bf16->fp32 expansion = SHL/AND (alu pipe).
__device__ __forceinline__ void acc8(float* acc, uint4 u, float wt) {
    acc[0] = fmaf(wt, __uint_as_float(u.x << 16),          acc[0]);
    acc[1] = fmaf(wt, __uint_as_float(u.x & 0xFFFF0000u),  acc[1]);
    acc[2] = fmaf(wt, __uint_as_float(u.y << 16),          acc[2]);
    acc[3] = fmaf(wt, __uint_as_float(u.y & 0xFFFF0000u),  acc[3]);
    acc[4] = fmaf(wt, __uint_as_float(u.z << 16),          acc[4]);
    acc[5] = fmaf(wt, __uint_as_float(u.z & 0xFFFF0000u),  acc[5]);
    acc[6] = fmaf(wt, __uint_as_float(u.w << 16),          acc[6]);
    acc[7] = fmaf(wt, __uint_as_float(u.w & 0xFFFF0000u),  acc[7]);
}

__global__ void k_agg() {
    int row = (blockIdx.x * blockDim.x + threadIdx.x) >> 5;
    int lane = threadIdx.x & 31;
    if (row >= NN) return;
    int beg = g_rowoff[row];
    int end = g_rowoff[row + 1];
    int half = lane >> 4, hl = lane & 15;
    const uint4* T4 = (const uint4*)g_feat;   // row = 16 uint4
    float acc[8] = {};
    int e = beg;
    for (; e + 3 < end; e += 4) {
        int2 cwA = g_cw[e + half];
        int2 cwB = g_cw[e + 2 + half];
        uint4 uA = __ldg(&T4[(unsigned)cwA.x * 16u + hl]);
        uint4 uB = __ldg(&T4[(unsigned)cwB.x * 16u + hl]);
        acc8(acc, uA, __int_as_float(cwA.y));
        acc8(acc, uB, __int_as_float(cwB.y));
    }
    for (; e < end; e += 2) {
        bool ok = (e + half) < end;
        int2 cw = ok ? g_cw[e + half] : make_int2(0, 0);
        float wt = ok ? __int_as_float(cw.y) : 0.f;
        uint4 u = __ldg(&T4[(unsigned)cw.x * 16u + hl]);
        acc8(acc, u, wt);
    }
    // combine the two half-warps (same cols, disjoint edge subsets)
#pragma unroll
    for (int j = 0; j < 8; j++)
        acc[j] += __shfl_xor_sync(0xFFFFFFFFu, acc[j], 16);
    // redistribute: lane l wants cols 4l..4l+3 (owner hl = l>>1, offset (l&1)*4)
    int srcl = lane >> 1;
    float t0 = __shfl_sync(0xFFFFFFFFu, acc[0], srcl);
    float t1 = __shfl_sync(0xFFFFFFFFu, acc[1], srcl);
    float t2 = __shfl_sync(0xFFFFFFFFu, acc[2], srcl);
    float t3 = __shfl_sync(0xFFFFFFFFu, acc[3], srcl);
    float t4 = __shfl_sync(0xFFFFFFFFu, acc[4], srcl);
    float t5 = __shfl_sync(0xFFFFFFFFu, acc[5], srcl);
    float t6 = __shfl_sync(0xFFFFFFFFu, acc[6], srcl);
    float t7 = __shfl_sync(0xFFFFFFFFu, acc[7], srcl);
    bool odd = (lane & 1);
    float4 r;
    r.x = odd ? t4 : t0; r.y = odd ? t5 : t1;
    r.z = odd ? t6 : t2; r.w = odd ? t7 : t3;
    // assemble this lane's A-image cell via shfl (lane = cell index)
    __half2 h01 = __floats2half2_rn(r.x, r.y);
    __half2 h23 = __floats2half2_rn(r.z, r.w);
    unsigned w01 = *(unsigned*)&h01, w23 = *(unsigned*)&h23;
    int kk = lane >> 2, q = lane & 3;
    int lA = 4 * kk + (q >> 1);
    int lB = lA + 2;
    unsigned a01 = __shfl_sync(0xFFFFFFFFu, w01, lA);
    unsigned a23 = __shfl_sync(0xFFFFFFFFu, w23, lA);
    unsigned b01 = __shfl_sync(0xFFFFFFFFu, w01, lB);
    unsigned b23 = __shfl_sync(0xFFFFFFFFu, w23, lB);
    unsigned wa = (q & 1) ? a23 : a01;
    unsigned wb = (q & 1) ? b23 : b01;
    g_Aimg[(size_t)row * 32 + lane] = make_uint2(wa, wb);
}

// ---------------- tensor-core GEMM (mma.sync fp16) + bias/relu epilogue --------
// block = 128x128 tile, 8 warps 4rg x 2cg, warp = 32x64; A+B both smem-staged.
// mode 0: +bias, relu, write bf16 g_feat. mode 1: +bias, write fp32 g_bufB.
#define SM_B_OFF 32768
#define GSM (32768 + 40960)   // 72 KB/CTA; 2 CTAs/SM

#define MMA_F16(C, A0, A1, A2, A3, B0, B1) \
    asm volatile("mma.sync.aligned.m16n8k16.row.col.f32.f16.f16.f32 " \
                 "{%0,%1,%2,%3}, {%4,%5,%6,%7}, {%8,%9}, {%0,%1,%2,%3};" \
                 : "+f"((C)[0]), "+f"((C)[1]), "+f"((C)[2]), "+f"((C)[3]) \
                 : "r"(A0), "r"(A1), "r"(A2), "r"(A3), "r"(B0), "r"(B1))

__global__ void __launch_bounds__(256, 2) k_gemm_mma(int layer,
                                                     const float* __restrict__ bias,
                                                     int mode) {
    extern __shared__ char smem[];
    uint2* sA = (uint2*)smem;                    // 4096 uint2, swizzled cells
    const uint4* pB = (const uint4*)(smem + SM_B_OFF);
    int tid = threadIdx.x;
    int row0 = blockIdx.x << 7;

    // stage B cell image: 2560 uint4 = 40 KB
    {
        const uint4* src = g_Wiv + layer * 2560;
        uint4* dst = (uint4*)(smem + SM_B_OFF);
#pragma unroll
        for (int it = 0; it < 10; it++) {
            int i = it * 256 + tid;
            dst[i] = __ldg(&src[i]);
        }
    }
    // stage A tile: 2048 uint4 = 32 KB, swizzle cell kk ^= row&7
    {
        const uint4* src = (const uint4*)(g_Aimg + (size_t)row0 * 32);
#pragma unroll
        for (int it = 0; it < 8; it++) {
            int i = it * 256 + tid;              // uint4 = 2 cells
            uint4 v = __ldg(&src[i]);
            int r = i >> 4;
            int c2 = (i & 15) * 2;               // even cell index
            int kk = c2 >> 2, q = c2 & 3;        // q in {0,2}
            int dstc = ((kk ^ (r & 7)) << 2) + q;
            *(uint4*)&sA[r * 32 + dstc] = v;
        }
    }
    __syncthreads();

    int lane = tid & 31, warp = tid >> 5;
    int rq = lane >> 2;        // 0..7
    int q = lane & 3;          // 0..3
    int rg = warp >> 1, cg = warp & 1;
    int wr = rg * 32 + rq;
    int ncol0 = cg * 64;

    float c[2][8][4] = {};

    const uint2* aRow0 = sA + (wr +  0) * 32 + q;
    const uint2* aRow1 = sA + (wr +  8) * 32 + q;
    const uint2* aRow2 = sA + (wr + 16) * 32 + q;
    const uint2* aRow3 = sA + (wr + 24) * 32 + q;
    const uint4* bBase = pB + (ncol0 + rq) * 20 + q;

#pragma unroll
    for (int j = 0; j < 4; j++) {
        int swa = ((2 * j) ^ rq) << 2;
        int swb = ((2 * j + 1) ^ rq) << 2;
        uint2 Aa0 = aRow0[swa], Aa1 = aRow1[swa];
        uint2 Aa2 = aRow2[swa], Aa3 = aRow3[swa];
        uint2 Ab0 = aRow0[swb], Ab1 = aRow1[swb];
        uint2 Ab2 = aRow2[swb], Ab3 = aRow3[swb];
        const uint4* bp = bBase + j * 4;
#pragma unroll
        for (int t = 0; t < 8; t++) {
            uint4 B = bp[t * 8 * 20];
            MMA_F16(c[0][t], Aa0.x, Aa1.x, Aa0.y, Aa1.y, B.x, B.y);
            MMA_F16(c[1][t], Aa2.x, Aa3.x, Aa2.y, Aa3.y, B.x, B.y);
            MMA_F16(c[0][t], Ab0.x, Ab1.x, Ab0.y, Ab1.y, B.z, B.w);
            MMA_F16(c[1][t], Ab2.x, Ab3.x, Ab2.y, Ab3.y, B.z, B.w);
        }
    }

    // epilogue: + bias, optional relu, bf16 or fp32 stores
    int wrow = row0 + rg * 32;
#pragma unroll
    for (int mb = 0; mb < 2; mb++) {
        int r1 = wrow + mb * 16 + rq, r2 = r1 + 8;
#pragma unroll
        for (int t = 0; t < 8; t++) {
            int col = ncol0 + t * 8 + q * 2;
            float2 bb = *(const float2*)(bias + col);
            float v0 = c[mb][t][0] + bb.x, v1 = c[mb][t][1] + bb.y;
            float v2 = c[mb][t][2] + bb.x, v3 = c[mb][t][3] + bb.y;
            if (mode == 0) {
                v0 = fmaxf(v0, 0.f); v1 = fmaxf(v1, 0.f);
                v2 = fmaxf(v2, 0.f); v3 = fmaxf(v3, 0.f);
                if (r1 < NN) {
                    __nv_bfloat162 h = __floats2bfloat162_rn(v0, v1);
                    g_feat[(size_t)r1 * 64 + (col >> 1)] = *(unsigned*)&h;
                }
                if (r2 < NN) {
                    __nv_bfloat162 h = __floats2bfloat162_rn(v2, v3);
                    g_feat[(size_t)r2 * 64 + (col >> 1)] = *(unsigned*)&h;
                }
            } else {
                if (r1 < NN) *(float2*)(g_bufB + (size_t)r1 * 128 + col) = make_float2(v0, v1);
                if (r2 < NN) *(float2*)(g_bufB + (size_t)r2 * 128 + col) = make_float2(v2, v3);
            }
        }
    }
}

// ---------------- pooling (+ deg cleanup for next run) --------------------------
__global__ void k_pool() {
    int gid = blockIdx.x * 128 + threadIdx.x;
    for (int i = gid; i < NN; i += 512 * 128) { g_deg[i] = 0; }
    int g = blockIdx.x >> 3;
    int s = blockIdx.x & 7;
    int col = threadIdx.x;
    int start = g_goff[g];
    int cnt = g_goff[g + 1] - start;
    int chunk = (cnt + 7) >> 3;
    int lo = start + s * chunk;
    int hi = lo + chunk;
    int ge = start + cnt;
    if (hi > ge) hi = ge;
    float sum = 0.f;
    int i = lo;
    for (; i + 3 < hi; i += 4) {
        sum += g_bufB[(size_t)(i + 0) * 128 + col];
        sum += g_bufB[(size_t)(i + 1) * 128 + col];
        sum += g_bufB[(size_t)(i + 2) * 128 + col];
        sum += g_bufB[(size_t)(i + 3) * 128 + col];
    }
    for (; i < hi; i++) sum += g_bufB[(size_t)i * 128 + col];
    if (lo < hi) atomicAdd(&g_pool[g * 128 + col], sum);
}

// ---------------- MLP head (+ pool cleanup for next run) ------------------------
__global__ void k_mlp(const float* __restrict__ Wo1, const float* __restrict__ bo1,
                      const float* __restrict__ Wo2, const float* __restrict__ bo2,
                      float* __restrict__ out) {
    __shared__ float ps[128];
    __shared__ float zs[64];
    int g = blockIdx.x;
    int t = threadIdx.x;
    int cnt = g_goff[g + 1] - g_goff[g];
    float inv = 1.0f / fmaxf((float)cnt, 1.0f);
    ps[t]      = g_pool[g * 128 + t] * inv;
    ps[t + 64] = g_pool[g * 128 + t + 64] * inv;
    g_pool[g * 128 + t] = 0.f;          // self-clean for next run
    g_pool[g * 128 + t + 64] = 0.f;
    __syncthreads();
    float z = bo1[t];
#pragma unroll 8
    for (int k = 0; k < 128; k++) z = fmaf(ps[k], Wo1[k * 64 + t], z);
    zs[t] = fmaxf(z, 0.f);
    __syncthreads();
    if (t < OUTD) {
        float o = bo2[t];
#pragma unroll 8
        for (int j = 0; j < 64; j++) o = fmaf(zs[j], Wo2[j * 32 + t], o);
        out[g * OUTD + t] = o;
    }
}

// ---------------- launch ------------------------------------------------------------
extern "C" void kernel_launch(void* const* d_in, const int* in_sizes, int n_in,
                              void* d_out, int out_size) {
    const float* x    = (const float*)d_in[0];
    const int*   ei   = (const int*)d_in[1];
    const int*   batch= (const int*)d_in[2];
    const float* W1   = (const float*)d_in[3];
    const float* b1   = (const float*)d_in[4];
    const float* W2   = (const float*)d_in[5];
    const float* b2   = (const float*)d_in[6];
    const float* W3   = (const float*)d_in[7];
    const float* b3   = (const float*)d_in[8];
    const float* Wo1  = (const float*)d_in[9];
    const float* bo1  = (const float*)d_in[10];
    const float* Wo2  = (const float*)d_in[11];
    const float* bo2  = (const float*)d_in[12];
    float* out = (float*)d_out;

    cudaFuncSetAttribute(k_gemm_mma, cudaFuncAttributeMaxDynamicSharedMemorySize, GSM);

    const int PREP_TASKS = NN * 32 + 3 * 2048;
    const int GEMM_BLOCKS = (NN + 127) / 128;
    const int AGG_BLOCKS  = (NN + 7) / 8;

    k_prep<<<(PREP_TASKS + 255) / 256, 256>>>(x, ei, batch, W1, W2, W3);  // 0
    k_scan<<<SCAN_PARTS, SCAN_CHUNK>>>();                                 // 1
    k_fill<<<(NEDGE + 255) / 256, 256>>>(ei);                             // 2
    k_agg<<<AGG_BLOCKS, 256>>>();                                         // 3 <- ncu slot
    k_gemm_mma<<<GEMM_BLOCKS, 256, GSM>>>(0, b1, 0);                      // 4
    k_agg<<<AGG_BLOCKS, 256>>>();                                         // 5
    k_gemm_mma<<<GEMM_BLOCKS, 256, GSM>>>(1, b2, 0);                      // 6
    k_agg<<<AGG_BLOCKS, 256>>>();                                         // 7
    k_gemm_mma<<<GEMM_BLOCKS, 256, GSM>>>(2, b3, 1);                      // 8
    k_pool<<<GG * 8, 128>>>();                                            // 9
    k_mlp<<<GG, 64>>>(Wo1, bo1, Wo2, bo2, out);                           // 10
}

// round 16
// speedup vs baseline: 1.0577x; 1.0577x over previous
#include <cuda_runtime.h>
#include <cuda_fp16.h>
#include <cuda_bf16.h>
#include <cstdint>

#define NN 100000
#define NN_PAD 100096
#define EE 1600000
#define NEDGE (EE + NN)
#define HH 128
#define GG 64
#define OUTD 32

// ---------------- scratch (device globals; zero at module load) ----------------
// Self-cleaning per run: deg (k_pool), gcnt (k_scan blk0), pool (k_mlp),
// cursor (k_prep), aggflag (k_fill). Aimg pad rows: never written, stay zero.
__device__ int    g_deg[NN];
__device__ float  g_dinv[NN];
__device__ int    g_rowoff[NN + 1];
__device__ int    g_cursor[NN];
__device__ int2   g_cw[NEDGE];                    // packed (col, w bits)
__device__ unsigned g_bufBh[(size_t)NN * 64];     // layer-3 GEMM output, bf16x2 (pool input)
__device__ unsigned g_feat[(size_t)NN * 64];      // bf16x2 features for gather
__device__ uint2  g_Aimg[(size_t)NN_PAD * 32];    // agg out: fp16 fragment-permuted cells
__device__ uint4  g_Wiv[3 * 2560];                // W^T fp16 paired-kk cells, [128][20]
__device__ float  g_pool[GG * HH];
__device__ int    g_gcnt[GG];
__device__ int    g_goff[GG + 1];
__device__ volatile int g_aggval[128];
__device__ volatile int g_aggflag[128];

// ---------------- fused prep: g_feat = bf16(x) + counts + W images -------------
__global__ void k_prep(const float* __restrict__ x, const int* __restrict__ ei,
                       const int* __restrict__ batch,
                       const float* __restrict__ W1, const float* __restrict__ W2,
                       const float* __restrict__ W3) {
    int idx = blockIdx.x * blockDim.x + threadIdx.x;
    if (idx < NN * 32) {
        int row = idx >> 5, c = idx & 31;
        const float4* xr4 = (const float4*)(x + (size_t)row * 128);
        float4 v = xr4[c];
        __nv_bfloat162 h0 = __floats2bfloat162_rn(v.x, v.y);
        __nv_bfloat162 h1 = __floats2bfloat162_rn(v.z, v.w);
        ((uint2*)g_feat)[(size_t)row * 32 + c] = make_uint2(*(unsigned*)&h0, *(unsigned*)&h1);
        if (idx < NN) { g_cursor[idx] = 0; atomicAdd(&g_gcnt[batch[idx]], 1); }
        if (idx < EE) atomicAdd(&g_deg[ei[EE + idx]], 1);
    } else {
        int r = idx - NN * 32;
        if (r < 3 * 2048) {
            int l = r >> 11, rr = r & 2047;
            const float* W = (l == 0) ? W1 : (l == 1) ? W2 : W3;
            int n = rr >> 4, c = rr & 15;
            int j = c >> 2, q = c & 3;
            int ka = 32 * j + 2 * q;
            int kb = ka + 16;
            __half2 x0 = __floats2half2_rn(W[(size_t)ka * 128 + n],       W[(size_t)(ka + 1) * 128 + n]);
            __half2 y0 = __floats2half2_rn(W[(size_t)(ka + 8) * 128 + n], W[(size_t)(ka + 9) * 128 + n]);
            __half2 z0 = __floats2half2_rn(W[(size_t)kb * 128 + n],       W[(size_t)(kb + 1) * 128 + n]);
            __half2 w0 = __floats2half2_rn(W[(size_t)(kb + 8) * 128 + n], W[(size_t)(kb + 9) * 128 + n]);
            uint4 cell;
            cell.x = *(unsigned*)&x0; cell.y = *(unsigned*)&y0;
            cell.z = *(unsigned*)&z0; cell.w = *(unsigned*)&w0;
            g_Wiv[l * 2560 + n * 20 + c] = cell;
        }
    }
}

// ---------------- single-kernel scan (decoupled lookback, 98 blocks) -----------
#define SCAN_CHUNK 1024
#define SCAN_PARTS ((NN + SCAN_CHUNK - 1) / SCAN_CHUNK)

__global__ void k_scan() {
    __shared__ int s[SCAN_CHUNK];
    __shared__ int sbase;
    int t = threadIdx.x;
    int bid = blockIdx.x;
    int i = bid * SCAN_CHUNK + t;
    int v = 0;
    if (i < NN) {
        v = g_deg[i] + 1;
        g_dinv[i] = rsqrtf((float)v);
    }
    s[t] = v; __syncthreads();
    for (int off = 1; off < SCAN_CHUNK; off <<= 1) {
        int x = (t >= off) ? s[t - off] : 0;
        __syncthreads();
        s[t] += x;
        __syncthreads();
    }
    if (t == 0) {
        sbase = 0;
        g_aggval[bid] = s[SCAN_CHUNK - 1];
        __threadfence();
        g_aggflag[bid] = 1;
        if (bid == 0) {
            int g = 0;
            for (int qq = 0; qq < GG; qq++) {
                g_goff[qq] = g;
                g += g_gcnt[qq];
                g_gcnt[qq] = 0;            // self-clean for next run
            }
            g_goff[GG] = g;
            g_rowoff[NN] = NEDGE;
        }
    }
    __syncthreads();
    if (t < bid) {
        while (g_aggflag[t] == 0) { __nanosleep(64); }
        atomicAdd_block(&sbase, g_aggval[t]);
    }
    __syncthreads();
    if (i < NN) g_rowoff[i] = sbase + s[t] - v;
}

__global__ void k_fill(const int* __restrict__ ei) {
    int idx = blockIdx.x * blockDim.x + threadIdx.x;
    if (idx < 128) g_aggflag[idx] = 0;     // self-clean for next run
    if (idx >= NEDGE) return;
    int s, d;
    if (idx < EE) { s = ei[idx]; d = ei[EE + idx]; }
    else          { s = d = idx - EE; }
    int pos = g_rowoff[d] + atomicAdd(&g_cursor[d], 1);
    float w = g_dinv[s] * g_dinv[d];
    g_cw[pos] = make_int2(s, __float_as_int(w));
}

// ---------------- CSR aggregation (bf16 gather, deep-unrolled): Aimg -----------
// warp per dst row; half-warp owns the 256B bf16 row (uint4/lane).
// Halves take CONSECUTIVE edge pairs -> one int4 LDG = 2 edge records.
// 8-edge main loop: 4 feature uint4 + 2 edge int4 in flight per thread.
__device__ __forceinline__ void acc8(float* acc, uint4 u, float wt) {
    acc[0] = fmaf(wt, __uint_as_float(u.x << 16),          acc[0]);
    acc[1] = fmaf(wt, __uint_as_float(u.x & 0xFFFF0000u),  acc[1]);
    acc[2] = fmaf(wt, __uint_as_float(u.y << 16),          acc[2]);
    acc[3] = fmaf(wt, __uint_as_float(u.y & 0xFFFF0000u),  acc[3]);
    acc[4] = fmaf(wt, __uint_as_float(u.z << 16),          acc[4]);
    acc[5] = fmaf(wt, __uint_as_float(u.z & 0xFFFF0000u),  acc[5]);
    acc[6] = fmaf(wt, __uint_as_float(u.w << 16),          acc[6]);
    acc[7] = fmaf(wt, __uint_as_float(u.w & 0xFFFF0000u),  acc[7]);
}

__global__ void k_agg() {
    int row = (blockIdx.x * blockDim.x + threadIdx.x) >> 5;
    int lane = threadIdx.x & 31;
    if (row >= NN) return;
    int beg = g_rowoff[row];
    int end = g_rowoff[row + 1];
    int half = lane >> 4, hl = lane & 15;
    const uint4* T4 = (const uint4*)g_feat;   // row = 16 uint4
    float acc[8] = {};
    // peel one edge if beg is odd (keeps int4 edge loads 16B-aligned)
    if (beg & 1) {
        int2 cw = g_cw[beg];
        float wt = (half == 0) ? __int_as_float(cw.y) : 0.f;
        uint4 u = __ldg(&T4[(unsigned)cw.x * 16u + hl]);
        acc8(acc, u, wt);
        beg++;
    }
    int e = beg;
    for (; e + 7 < end; e += 8) {
        int4 ed0 = *(const int4*)&g_cw[e + 4 * half];       // edges e+4h, e+4h+1
        int4 ed1 = *(const int4*)&g_cw[e + 4 * half + 2];   // edges e+4h+2, e+4h+3
        uint4 u0 = __ldg(&T4[(unsigned)ed0.x * 16u + hl]);
        uint4 u1 = __ldg(&T4[(unsigned)ed0.z * 16u + hl]);
        uint4 u2 = __ldg(&T4[(unsigned)ed1.x * 16u + hl]);
        uint4 u3 = __ldg(&T4[(unsigned)ed1.z * 16u + hl]);
        acc8(acc, u0, __int_as_float(ed0.y));
        acc8(acc, u1, __int_as_float(ed0.w));
        acc8(acc, u2, __int_as_float(ed1.y));
        acc8(acc, u3, __int_as_float(ed1.w));
    }
    for (; e + 3 < end; e += 4) {
        int4 ed = *(const int4*)&g_cw[e + 2 * half];        // edges e+2h, e+2h+1
        uint4 u0 = __ldg(&T4[(unsigned)ed.x * 16u + hl]);
        uint4 u1 = __ldg(&T4[(unsigned)ed.z * 16u + hl]);
        acc8(acc, u0, __int_as_float(ed.y));
        acc8(acc, u1, __int_as_float(ed.w));
    }
    for (; e < end; e += 2) {
        bool ok = (e + half) < end;
        int2 cw = ok ? g_cw[e + half] : make_int2(0, 0);
        float wt = ok ? __int_as_float(cw.y) : 0.f;
        uint4 u = __ldg(&T4[(unsigned)cw.x * 16u + hl]);
        acc8(acc, u, wt);
    }
    // combine the two half-warps (same cols, disjoint edge subsets)
#pragma unroll
    for (int j = 0; j < 8; j++)
        acc[j] += __shfl_xor_sync(0xFFFFFFFFu, acc[j], 16);
    // redistribute: lane l wants cols 4l..4l+3 (owner hl = l>>1, offset (l&1)*4)
    int srcl = lane >> 1;
    float t0 = __shfl_sync(0xFFFFFFFFu, acc[0], srcl);
    float t1 = __shfl_sync(0xFFFFFFFFu, acc[1], srcl);
    float t2 = __shfl_sync(0xFFFFFFFFu, acc[2], srcl);
    float t3 = __shfl_sync(0xFFFFFFFFu, acc[3], srcl);
    float t4 = __shfl_sync(0xFFFFFFFFu, acc[4], srcl);
    float t5 = __shfl_sync(0xFFFFFFFFu, acc[5], srcl);
    float t6 = __shfl_sync(0xFFFFFFFFu, acc[6], srcl);
    float t7 = __shfl_sync(0xFFFFFFFFu, acc[7], srcl);
    bool odd = (lane & 1);
    float4 r;
    r.x = odd ? t4 : t0; r.y = odd ? t5 : t1;
    r.z = odd ? t6 : t2; r.w = odd ? t7 : t3;
    // assemble this lane's A-image cell via shfl (lane = cell index)
    __half2 h01 = __floats2half2_rn(r.x, r.y);
    __half2 h23 = __floats2half2_rn(r.z, r.w);
    unsigned w01 = *(unsigned*)&h01, w23 = *(unsigned*)&h23;
    int kk = lane >> 2, q = lane & 3;
    int lA = 4 * kk + (q >> 1);
    int lB = lA + 2;
    unsigned a01 = __shfl_sync(0xFFFFFFFFu, w01, lA);
    unsigned a23 = __shfl_sync(0xFFFFFFFFu, w23, lA);
    unsigned b01 = __shfl_sync(0xFFFFFFFFu, w01, lB);
    unsigned b23 = __shfl_sync(0xFFFFFFFFu, w23, lB);
    unsigned wa = (q & 1) ? a23 : a01;
    unsigned wb = (q & 1) ? b23 : b01;
    g_Aimg[(size_t)row * 32 + lane] = make_uint2(wa, wb);
}

// ---------------- tensor-core GEMM (mma.sync fp16) + bias/relu epilogue --------
// block = 128x128 tile, 8 warps 4rg x 2cg, warp = 32x64; A+B both smem-staged.
// mode 0: +bias, relu, write bf16 g_feat. mode 1: +bias, write bf16 g_bufBh.
#define SM_B_OFF 32768
#define GSM (32768 + 40960)   // 72 KB/CTA; 2 CTAs/SM

#define MMA_F16(C, A0, A1, A2, A3, B0, B1) \
    asm volatile("mma.sync.aligned.m16n8k16.row.col.f32.f16.f16.f32 " \
                 "{%0,%1,%2,%3}, {%4,%5,%6,%7}, {%8,%9}, {%0,%1,%2,%3};" \
                 : "+f"((C)[0]), "+f"((C)[1]), "+f"((C)[2]), "+f"((C)[3]) \
                 : "r"(A0), "r"(A1), "r"(A2), "r"(A3), "r"(B0), "r"(B1))

__global__ void __launch_bounds__(256, 2) k_gemm_mma(int layer,
                                                     const float* __restrict__ bias,
                                                     int mode) {
    extern __shared__ char smem[];
    uint2* sA = (uint2*)smem;                    // 4096 uint2, swizzled cells
    const uint4* pB = (const uint4*)(smem + SM_B_OFF);
    int tid = threadIdx.x;
    int row0 = blockIdx.x << 7;

    // stage B cell image: 2560 uint4 = 40 KB
    {
        const uint4* src = g_Wiv + layer * 2560;
        uint4* dst = (uint4*)(smem + SM_B_OFF);
#pragma unroll
        for (int it = 0; it < 10; it++) {
            int i = it * 256 + tid;
            dst[i] = __ldg(&src[i]);
        }
    }
    // stage A tile: 2048 uint4 = 32 KB, swizzle cell kk ^= row&7
    {
        const uint4* src = (const uint4*)(g_Aimg + (size_t)row0 * 32);
#pragma unroll
        for (int it = 0; it < 8; it++) {
            int i = it * 256 + tid;              // uint4 = 2 cells
            uint4 v = __ldg(&src[i]);
            int r = i >> 4;
            int c2 = (i & 15) * 2;               // even cell index
            int kk = c2 >> 2, q = c2 & 3;        // q in {0,2}
            int dstc = ((kk ^ (r & 7)) << 2) + q;
            *(uint4*)&sA[r * 32 + dstc] = v;
        }
    }
    __syncthreads();

    int lane = tid & 31, warp = tid >> 5;
    int rq = lane >> 2;        // 0..7
    int q = lane & 3;          // 0..3
    int rg = warp >> 1, cg = warp & 1;
    int wr = rg * 32 + rq;
    int ncol0 = cg * 64;

    float c[2][8][4] = {};

    const uint2* aRow0 = sA + (wr +  0) * 32 + q;
    const uint2* aRow1 = sA + (wr +  8) * 32 + q;
    const uint2* aRow2 = sA + (wr + 16) * 32 + q;
    const uint2* aRow3 = sA + (wr + 24) * 32 + q;
    const uint4* bBase = pB + (ncol0 + rq) * 20 + q;

#pragma unroll
    for (int j = 0; j < 4; j++) {
        int swa = ((2 * j) ^ rq) << 2;
        int swb = ((2 * j + 1) ^ rq) << 2;
        uint2 Aa0 = aRow0[swa], Aa1 = aRow1[swa];
        uint2 Aa2 = aRow2[swa], Aa3 = aRow3[swa];
        uint2 Ab0 = aRow0[swb], Ab1 = aRow1[swb];
        uint2 Ab2 = aRow2[swb], Ab3 = aRow3[swb];
        const uint4* bp = bBase + j * 4;
#pragma unroll
        for (int t = 0; t < 8; t++) {
            uint4 B = bp[t * 8 * 20];
            MMA_F16(c[0][t], Aa0.x, Aa1.x, Aa0.y, Aa1.y, B.x, B.y);
            MMA_F16(c[1][t], Aa2.x, Aa3.x, Aa2.y, Aa3.y, B.x, B.y);
            MMA_F16(c[0][t], Ab0.x, Ab1.x, Ab0.y, Ab1.y, B.z, B.w);
            MMA_F16(c[1][t], Ab2.x, Ab3.x, Ab2.y, Ab3.y, B.z, B.w);
        }
    }

    // epilogue: + bias, optional relu, bf16 stores
    int wrow = row0 + rg * 32;
#pragma unroll
    for (int mb = 0; mb < 2; mb++) {
        int r1 = wrow + mb * 16 + rq, r2 = r1 + 8;
#pragma unroll
        for (int t = 0; t < 8; t++) {
            int col = ncol0 + t * 8 + q * 2;
            float2 bb = *(const float2*)(bias + col);
            float v0 = c[mb][t][0] + bb.x, v1 = c[mb][t][1] + bb.y;
            float v2 = c[mb][t][2] + bb.x, v3 = c[mb][t][3] + bb.y;
            if (mode == 0) {
                v0 = fmaxf(v0, 0.f); v1 = fmaxf(v1, 0.f);
                v2 = fmaxf(v2, 0.f); v3 = fmaxf(v3, 0.f);
                if (r1 < NN) {
                    __nv_bfloat162 h = __floats2bfloat162_rn(v0, v1);
                    g_feat[(size_t)r1 * 64 + (col >> 1)] = *(unsigned*)&h;
                }
                if (r2 < NN) {
                    __nv_bfloat162 h = __floats2bfloat162_rn(v2, v3);
                    g_feat[(size_t)r2 * 64 + (col >> 1)] = *(unsigned*)&h;
                }
            } else {
                if (r1 < NN) {
                    __nv_bfloat162 h = __floats2bfloat162_rn(v0, v1);
                    g_bufBh[(size_t)r1 * 64 + (col >> 1)] = *(unsigned*)&h;
                }
                if (r2 < NN) {
                    __nv_bfloat162 h = __floats2bfloat162_rn(v2, v3);
                    g_bufBh[(size_t)r2 * 64 + (col >> 1)] = *(unsigned*)&h;
                }
            }
        }
    }
}

// ---------------- pooling over bf16 layer-3 output (+ deg cleanup) --------------
__global__ void k_pool() {
    int gid = blockIdx.x * 128 + threadIdx.x;
    for (int i = gid; i < NN; i += 512 * 128) { g_deg[i] = 0; }
    int g = blockIdx.x >> 3;
    int s = blockIdx.x & 7;
    int col = threadIdx.x;
    int w2 = col >> 1;
    bool odd = col & 1;
    int start = g_goff[g];
    int cnt = g_goff[g + 1] - start;
    int chunk = (cnt + 7) >> 3;
    int lo = start + s * chunk;
    int hi = lo + chunk;
    int ge = start + cnt;
    if (hi > ge) hi = ge;
    float sum = 0.f;
    int i = lo;
    for (; i + 3 < hi; i += 4) {
        unsigned a = g_bufBh[(size_t)(i + 0) * 64 + w2];
        unsigned b = g_bufBh[(size_t)(i + 1) * 64 + w2];
        unsigned c = g_bufBh[(size_t)(i + 2) * 64 + w2];
        unsigned d = g_bufBh[(size_t)(i + 3) * 64 + w2];
        sum += odd ? __uint_as_float(a & 0xFFFF0000u) : __uint_as_float(a << 16);
        sum += odd ? __uint_as_float(b & 0xFFFF0000u) : __uint_as_float(b << 16);
        sum += odd ? __uint_as_float(c & 0xFFFF0000u) : __uint_as_float(c << 16);
        sum += odd ? __uint_as_float(d & 0xFFFF0000u) : __uint_as_float(d << 16);
    }
    for (; i < hi; i++) {
        unsigned a = g_bufBh[(size_t)i * 64 + w2];
        sum += odd ? __uint_as_float(a & 0xFFFF0000u) : __uint_as_float(a << 16);
    }
    if (lo < hi) atomicAdd(&g_pool[g * 128 + col], sum);
}

// ---------------- MLP head (+ pool cleanup for next run) ------------------------
__global__ void k_mlp(const float* __restrict__ Wo1, const float* __restrict__ bo1,
                      const float* __restrict__ Wo2, const float* __restrict__ bo2,
                      float* __restrict__ out) {
    __shared__ float ps[128];
    __shared__ float zs[64];
    int g = blockIdx.x;
    int t = threadIdx.x;
    int cnt = g_goff[g + 1] - g_goff[g];
    float inv = 1.0f / fmaxf((float)cnt, 1.0f);
    ps[t]      = g_pool[g * 128 + t] * inv;
    ps[t + 64] = g_pool[g * 128 + t + 64] * inv;
    g_pool[g * 128 + t] = 0.f;          // self-clean for next run
    g_pool[g * 128 + t + 64] = 0.f;
    __syncthreads();
    float z = bo1[t];
#pragma unroll 8
    for (int k = 0; k < 128; k++) z = fmaf(ps[k], Wo1[k * 64 + t], z);
    zs[t] = fmaxf(z, 0.f);
    __syncthreads();
    if (t < OUTD) {
        float o = bo2[t];
#pragma unroll 8
        for (int j = 0; j < 64; j++) o = fmaf(zs[j], Wo2[j * 32 + t], o);
        out[g * OUTD + t] = o;
    }
}

// ---------------- launch ------------------------------------------------------------
extern "C" void kernel_launch(void* const* d_in, const int* in_sizes, int n_in,
                              void* d_out, int out_size) {
    const float* x    = (const float*)d_in[0];
    const int*   ei   = (const int*)d_in[1];
    const int*   batch= (const int*)d_in[2];
    const float* W1   = (const float*)d_in[3];
    const float* b1   = (const float*)d_in[4];
    const float* W2   = (const float*)d_in[5];
    const float* b2   = (const float*)d_in[6];
    const float* W3   = (const float*)d_in[7];
    const float* b3   = (const float*)d_in[8];
    const float* Wo1  = (const float*)d_in[9];
    const float* bo1  = (const float*)d_in[10];
    const float* Wo2  = (const float*)d_in[11];
    const float* bo2  = (const float*)d_in[12];
    float* out = (float*)d_out;

    cudaFuncSetAttribute(k_gemm_mma, cudaFuncAttributeMaxDynamicSharedMemorySize, GSM);

    const int PREP_TASKS = NN * 32 + 3 * 2048;
    const int GEMM_BLOCKS = (NN + 127) / 128;
    const int AGG_BLOCKS  = (NN + 7) / 8;

    k_prep<<<(PREP_TASKS + 255) / 256, 256>>>(x, ei, batch, W1, W2, W3);  // 0
    k_scan<<<SCAN_PARTS, SCAN_CHUNK>>>();                                 // 1
    k_fill<<<(NEDGE + 255) / 256, 256>>>(ei);                             // 2
    k_agg<<<AGG_BLOCKS, 256>>>();                                         // 3 <- ncu slot
    k_gemm_mma<<<GEMM_BLOCKS, 256, GSM>>>(0, b1, 0);                      // 4
    k_agg<<<AGG_BLOCKS, 256>>>();                                         // 5
    k_gemm_mma<<<GEMM_BLOCKS, 256, GSM>>>(1, b2, 0);                      // 6
    k_agg<<<AGG_BLOCKS, 256>>>();                                         // 7
    k_gemm_mma<<<GEMM_BLOCKS, 256, GSM>>>(2, b3, 1);                      // 8
    k_pool<<<GG * 8, 128>>>();                                            // 9
    k_mlp<<<GG, 64>>>(Wo1, bo1, Wo2, bo2, out);                           // 10
}

// round 17
// speedup vs baseline: 1.0590x; 1.0012x over previous
#include <cuda_runtime.h>
#include <cuda_fp16.h>
#include <cuda_bf16.h>
#include <cstdint>

#define NN 100000
#define NN_PAD 100096
#define EE 1600000
#define NCW (EE + 8 * NN)     // padded CSR capacity
#define HH 128
#define GG 64
#define OUTD 32

// ---------------- scratch (device globals; zero at module load) ----------------
// Self-cleaning per run: deg (k_pool), gcnt (k_scan blk0), pool (k_mlp),
// aggflag (k_fill).
__device__ int    g_deg[NN];
__device__ float  g_dinv[NN];
__device__ int    g_rowoff[NN + 1];
__device__ int    g_rank[EE];                     // per-edge slot rank within dst row
__device__ int2   g_cw[NCW];                      // packed (col, w bits), rows padded to 8
__device__ unsigned g_bufBh[(size_t)NN * 64];     // layer-3 GEMM output, bf16x2 (pool input)
__device__ unsigned g_feat[(size_t)NN * 64];      // bf16x2 features for gather
__device__ uint2  g_Aimg[(size_t)NN_PAD * 32];    // agg out: fp16 fragment-permuted cells
__device__ uint4  g_Wiv[3 * 2560];                // W^T fp16 paired-kk cells, [128][20]
__device__ float  g_pool[GG * HH];
__device__ int    g_gcnt[GG];
__device__ int    g_goff[GG + 1];
__device__ volatile int g_aggval[128];
__device__ volatile int g_aggflag[128];

// ---------------- fused prep: g_feat = bf16(x) + deg/rank + counts + W images --
__global__ void k_prep(const float* __restrict__ x, const int* __restrict__ ei,
                       const int* __restrict__ batch,
                       const float* __restrict__ W1, const float* __restrict__ W2,
                       const float* __restrict__ W3) {
    int idx = blockIdx.x * blockDim.x + threadIdx.x;
    if (idx < NN * 32) {
        int row = idx >> 5, c = idx & 31;
        const float4* xr4 = (const float4*)(x + (size_t)row * 128);
        float4 v = xr4[c];
        __nv_bfloat162 h0 = __floats2bfloat162_rn(v.x, v.y);
        __nv_bfloat162 h1 = __floats2bfloat162_rn(v.z, v.w);
        ((uint2*)g_feat)[(size_t)row * 32 + c] = make_uint2(*(unsigned*)&h0, *(unsigned*)&h1);
        if (idx < NN) atomicAdd(&g_gcnt[batch[idx]], 1);
        if (idx < EE) g_rank[idx] = atomicAdd(&g_deg[ei[EE + idx]], 1);
    } else {
        int r = idx - NN * 32;
        if (r < 3 * 2048) {
            int l = r >> 11, rr = r & 2047;
            const float* W = (l == 0) ? W1 : (l == 1) ? W2 : W3;
            int n = rr >> 4, c = rr & 15;
            int j = c >> 2, q = c & 3;
            int ka = 32 * j + 2 * q;
            int kb = ka + 16;
            __half2 x0 = __floats2half2_rn(W[(size_t)ka * 128 + n],       W[(size_t)(ka + 1) * 128 + n]);
            __half2 y0 = __floats2half2_rn(W[(size_t)(ka + 8) * 128 + n], W[(size_t)(ka + 9) * 128 + n]);
            __half2 z0 = __floats2half2_rn(W[(size_t)kb * 128 + n],       W[(size_t)(kb + 1) * 128 + n]);
            __half2 w0 = __floats2half2_rn(W[(size_t)(kb + 8) * 128 + n], W[(size_t)(kb + 9) * 128 + n]);
            uint4 cell;
            cell.x = *(unsigned*)&x0; cell.y = *(unsigned*)&y0;
            cell.z = *(unsigned*)&z0; cell.w = *(unsigned*)&w0;
            g_Wiv[l * 2560 + n * 20 + c] = cell;
        }
    }
}

// ---------------- single-kernel scan of padded row sizes + pad fill ------------
#define SCAN_CHUNK 1024
#define SCAN_PARTS ((NN + SCAN_CHUNK - 1) / SCAN_CHUNK)

__global__ void k_scan() {
    __shared__ int s[SCAN_CHUNK];
    __shared__ int sbase;
    int t = threadIdx.x;
    int bid = blockIdx.x;
    int i = bid * SCAN_CHUNK + t;
    int d1 = 0, v = 0;
    if (i < NN) {
        d1 = g_deg[i] + 1;                  // edges + self loop
        v = (d1 + 7) & ~7;                  // padded to multiple of 8
        g_dinv[i] = rsqrtf((float)d1);
    }
    s[t] = v; __syncthreads();
    for (int off = 1; off < SCAN_CHUNK; off <<= 1) {
        int x = (t >= off) ? s[t - off] : 0;
        __syncthreads();
        s[t] += x;
        __syncthreads();
    }
    if (t == 0) {
        sbase = 0;
        g_aggval[bid] = s[SCAN_CHUNK - 1];
        __threadfence();
        g_aggflag[bid] = 1;
        if (bid == 0) {
            int g = 0;
            for (int qq = 0; qq < GG; qq++) {
                g_goff[qq] = g;
                g += g_gcnt[qq];
                g_gcnt[qq] = 0;            // self-clean for next run
            }
            g_goff[GG] = g;
        }
    }
    __syncthreads();
    if (t < bid) {
        while (g_aggflag[t] == 0) { __nanosleep(64); }
        atomicAdd_block(&sbase, g_aggval[t]);
    }
    __syncthreads();
    if (i < NN) {
        int off = sbase + s[t] - v;
        g_rowoff[i] = off;
        for (int j = d1; j < v; j++) g_cw[off + j] = make_int2(0, 0);   // zero pads
        if (i == NN - 1) g_rowoff[NN] = off + v;
    }
}

// ---------------- CSR fill: NO atomics (rank precomputed in k_prep) ------------
__global__ void k_fill(const int* __restrict__ ei) {
    int idx = blockIdx.x * blockDim.x + threadIdx.x;
    if (idx < 128) g_aggflag[idx] = 0;     // self-clean for next run
    if (idx >= EE + NN) return;
    int s, d, rank;
    if (idx < EE) { s = ei[idx]; d = ei[EE + idx]; rank = g_rank[idx]; }
    else          { s = d = idx - EE; rank = g_deg[d]; }   // self loop last
    float w = g_dinv[s] * g_dinv[d];
    g_cw[g_rowoff[d] + rank] = make_int2(s, __float_as_int(w));
}

// ---------------- CSR aggregation (branch-free 8-edge loop): Aimg --------------
// warp per dst row; half-warp owns the 256B bf16 row (uint4/lane).
// Rows padded to multiple of 8 -> single loop, no peel, no tails.
__device__ __forceinline__ void acc8(float* acc, uint4 u, float wt) {
    acc[0] = fmaf(wt, __uint_as_float(u.x << 16),          acc[0]);
    acc[1] = fmaf(wt, __uint_as_float(u.x & 0xFFFF0000u),  acc[1]);
    acc[2] = fmaf(wt, __uint_as_float(u.y << 16),          acc[2]);
    acc[3] = fmaf(wt, __uint_as_float(u.y & 0xFFFF0000u),  acc[3]);
    acc[4] = fmaf(wt, __uint_as_float(u.z << 16),          acc[4]);
    acc[5] = fmaf(wt, __uint_as_float(u.z & 0xFFFF0000u),  acc[5]);
    acc[6] = fmaf(wt, __uint_as_float(u.w << 16),          acc[6]);
    acc[7] = fmaf(wt, __uint_as_float(u.w & 0xFFFF0000u),  acc[7]);
}

__global__ void k_agg() {
    int row = (blockIdx.x * blockDim.x + threadIdx.x) >> 5;
    int lane = threadIdx.x & 31;
    if (row >= NN) return;
    int beg = g_rowoff[row];
    int end = g_rowoff[row + 1];
    int half = lane >> 4, hl = lane & 15;
    const uint4* T4 = (const uint4*)g_feat;   // row = 16 uint4
    float acc[8] = {};
    for (int e = beg; e < end; e += 8) {
        int4 ed0 = *(const int4*)&g_cw[e + 4 * half];       // edges e+4h, e+4h+1
        int4 ed1 = *(const int4*)&g_cw[e + 4 * half + 2];   // edges e+4h+2, e+4h+3
        uint4 u0 = __ldg(&T4[(unsigned)ed0.x * 16u + hl]);
        uint4 u1 = __ldg(&T4[(unsigned)ed0.z * 16u + hl]);
        uint4 u2 = __ldg(&T4[(unsigned)ed1.x * 16u + hl]);
        uint4 u3 = __ldg(&T4[(unsigned)ed1.z * 16u + hl]);
        acc8(acc, u0, __int_as_float(ed0.y));
        acc8(acc, u1, __int_as_float(ed0.w));
        acc8(acc, u2, __int_as_float(ed1.y));
        acc8(acc, u3, __int_as_float(ed1.w));
    }
    // combine the two half-warps (same cols, disjoint edge subsets)
#pragma unroll
    for (int j = 0; j < 8; j++)
        acc[j] += __shfl_xor_sync(0xFFFFFFFFu, acc[j], 16);
    // redistribute: lane l wants cols 4l..4l+3 (owner hl = l>>1, offset (l&1)*4)
    int srcl = lane >> 1;
    float t0 = __shfl_sync(0xFFFFFFFFu, acc[0], srcl);
    float t1 = __shfl_sync(0xFFFFFFFFu, acc[1], srcl);
    float t2 = __shfl_sync(0xFFFFFFFFu, acc[2], srcl);
    float t3 = __shfl_sync(0xFFFFFFFFu, acc[3], srcl);
    float t4 = __shfl_sync(0xFFFFFFFFu, acc[4], srcl);
    float t5 = __shfl_sync(0xFFFFFFFFu, acc[5], srcl);
    float t6 = __shfl_sync(0xFFFFFFFFu, acc[6], srcl);
    float t7 = __shfl_sync(0xFFFFFFFFu, acc[7], srcl);
    bool odd = (lane & 1);
    float4 r;
    r.x = odd ? t4 : t0; r.y = odd ? t5 : t1;
    r.z = odd ? t6 : t2; r.w = odd ? t7 : t3;
    // assemble this lane's A-image cell via shfl (lane = cell index)
    __half2 h01 = __floats2half2_rn(r.x, r.y);
    __half2 h23 = __floats2half2_rn(r.z, r.w);
    unsigned w01 = *(unsigned*)&h01, w23 = *(unsigned*)&h23;
    int kk = lane >> 2, q = lane & 3;
    int lA = 4 * kk + (q >> 1);
    int lB = lA + 2;
    unsigned a01 = __shfl_sync(0xFFFFFFFFu, w01, lA);
    unsigned a23 = __shfl_sync(0xFFFFFFFFu, w23, lA);
    unsigned b01 = __shfl_sync(0xFFFFFFFFu, w01, lB);
    unsigned b23 = __shfl_sync(0xFFFFFFFFu, w23, lB);
    unsigned wa = (q & 1) ? a23 : a01;
    unsigned wb = (q & 1) ? b23 : b01;
    g_Aimg[(size_t)row * 32 + lane] = make_uint2(wa, wb);
}

// ---------------- tensor-core GEMM (mma.sync fp16) + bias/relu epilogue --------
// block = 128x128 tile, 8 warps 4rg x 2cg, warp = 32x64; A+B both smem-staged.
// mode 0: +bias, relu, write bf16 g_feat. mode 1: +bias, write bf16 g_bufBh.
#define SM_B_OFF 32768
#define GSM (32768 + 40960)   // 72 KB/CTA; 2 CTAs/SM

#define MMA_F16(C, A0, A1, A2, A3, B0, B1) \
    asm volatile("mma.sync.aligned.m16n8k16.row.col.f32.f16.f16.f32 " \
                 "{%0,%1,%2,%3}, {%4,%5,%6,%7}, {%8,%9}, {%0,%1,%2,%3};" \
                 : "+f"((C)[0]), "+f"((C)[1]), "+f"((C)[2]), "+f"((C)[3]) \
                 : "r"(A0), "r"(A1), "r"(A2), "r"(A3), "r"(B0), "r"(B1))

__global__ void __launch_bounds__(256, 2) k_gemm_mma(int layer,
                                                     const float* __restrict__ bias,
                                                     int mode) {
    extern __shared__ char smem[];
    uint2* sA = (uint2*)smem;                    // 4096 uint2, swizzled cells
    const uint4* pB = (const uint4*)(smem + SM_B_OFF);
    int tid = threadIdx.x;
    int row0 = blockIdx.x << 7;

    // stage B cell image: 2560 uint4 = 40 KB
    {
        const uint4* src = g_Wiv + layer * 2560;
        uint4* dst = (uint4*)(smem + SM_B_OFF);
#pragma unroll
        for (int it = 0; it < 10; it++) {
            int i = it * 256 + tid;
            dst[i] = __ldg(&src[i]);
        }
    }
    // stage A tile: 2048 uint4 = 32 KB, swizzle cell kk ^= row&7
    {
        const uint4* src = (const uint4*)(g_Aimg + (size_t)row0 * 32);
#pragma unroll
        for (int it = 0; it < 8; it++) {
            int i = it * 256 + tid;              // uint4 = 2 cells
            uint4 v = __ldg(&src[i]);
            int r = i >> 4;
            int c2 = (i & 15) * 2;               // even cell index
            int kk = c2 >> 2, q = c2 & 3;        // q in {0,2}
            int dstc = ((kk ^ (r & 7)) << 2) + q;
            *(uint4*)&sA[r * 32 + dstc] = v;
        }
    }
    __syncthreads();

    int lane = tid & 31, warp = tid >> 5;
    int rq = lane >> 2;        // 0..7
    int q = lane & 3;          // 0..3
    int rg = warp >> 1, cg = warp & 1;
    int wr = rg * 32 + rq;
    int ncol0 = cg * 64;

    float c[2][8][4] = {};

    const uint2* aRow0 = sA + (wr +  0) * 32 + q;
    const uint2* aRow1 = sA + (wr +  8) * 32 + q;
    const uint2* aRow2 = sA + (wr + 16) * 32 + q;
    const uint2* aRow3 = sA + (wr + 24) * 32 + q;
    const uint4* bBase = pB + (ncol0 + rq) * 20 + q;

#pragma unroll
    for (int j = 0; j < 4; j++) {
        int swa = ((2 * j) ^ rq) << 2;
        int swb = ((2 * j + 1) ^ rq) << 2;
        uint2 Aa0 = aRow0[swa], Aa1 = aRow1[swa];
        uint2 Aa2 = aRow2[swa], Aa3 = aRow3[swa];
        uint2 Ab0 = aRow0[swb], Ab1 = aRow1[swb];
        uint2 Ab2 = aRow2[swb], Ab3 = aRow3[swb];
        const uint4* bp = bBase + j * 4;
#pragma unroll
        for (int t = 0; t < 8; t++) {
            uint4 B = bp[t * 8 * 20];
            MMA_F16(c[0][t], Aa0.x, Aa1.x, Aa0.y, Aa1.y, B.x, B.y);
            MMA_F16(c[1][t], Aa2.x, Aa3.x, Aa2.y, Aa3.y, B.x, B.y);
            MMA_F16(c[0][t], Ab0.x, Ab1.x, Ab0.y, Ab1.y, B.z, B.w);
            MMA_F16(c[1][t], Ab2.x, Ab3.x, Ab2.y, Ab3.y, B.z, B.w);
        }
    }

    // epilogue: + bias, optional relu, bf16 stores
    int wrow = row0 + rg * 32;
#pragma unroll
    for (int mb = 0; mb < 2; mb++) {
        int r1 = wrow + mb * 16 + rq, r2 = r1 + 8;
#pragma unroll
        for (int t = 0; t < 8; t++) {
            int col = ncol0 + t * 8 + q * 2;
            float2 bb = *(const float2*)(bias + col);
            float v0 = c[mb][t][0] + bb.x, v1 = c[mb][t][1] + bb.y;
            float v2 = c[mb][t][2] + bb.x, v3 = c[mb][t][3] + bb.y;
            if (mode == 0) {
                v0 = fmaxf(v0, 0.f); v1 = fmaxf(v1, 0.f);
                v2 = fmaxf(v2, 0.f); v3 = fmaxf(v3, 0.f);
                if (r1 < NN) {
                    __nv_bfloat162 h = __floats2bfloat162_rn(v0, v1);
                    g_feat[(size_t)r1 * 64 + (col >> 1)] = *(unsigned*)&h;
                }
                if (r2 < NN) {
                    __nv_bfloat162 h = __floats2bfloat162_rn(v2, v3);
                    g_feat[(size_t)r2 * 64 + (col >> 1)] = *(unsigned*)&h;
                }
            } else {
                if (r1 < NN) {
                    __nv_bfloat162 h = __floats2bfloat162_rn(v0, v1);
                    g_bufBh[(size_t)r1 * 64 + (col >> 1)] = *(unsigned*)&h;
                }
                if (r2 < NN) {
                    __nv_bfloat162 h = __floats2bfloat162_rn(v2, v3);
                    g_bufBh[(size_t)r2 * 64 + (col >> 1)] = *(unsigned*)&h;
                }
            }
        }
    }
}

// ---------------- pooling over bf16 layer-3 output (+ deg cleanup) --------------
__global__ void k_pool() {
    int gid = blockIdx.x * 128 + threadIdx.x;
    for (int i = gid; i < NN; i += 512 * 128) { g_deg[i] = 0; }
    int g = blockIdx.x >> 3;
    int s = blockIdx.x & 7;
    int col = threadIdx.x;
    int w2 = col >> 1;
    bool odd = col & 1;
    int start = g_goff[g];
    int cnt = g_goff[g + 1] - start;
    int chunk = (cnt + 7) >> 3;
    int lo = start + s * chunk;
    int hi = lo + chunk;
    int ge = start + cnt;
    if (hi > ge) hi = ge;
    float sum = 0.f;
    int i = lo;
    for (; i + 3 < hi; i += 4) {
        unsigned a = g_bufBh[(size_t)(i + 0) * 64 + w2];
        unsigned b = g_bufBh[(size_t)(i + 1) * 64 + w2];
        unsigned c = g_bufBh[(size_t)(i + 2) * 64 + w2];
        unsigned d = g_bufBh[(size_t)(i + 3) * 64 + w2];
        sum += odd ? __uint_as_float(a & 0xFFFF0000u) : __uint_as_float(a << 16);
        sum += odd ? __uint_as_float(b & 0xFFFF0000u) : __uint_as_float(b << 16);
        sum += odd ? __uint_as_float(c & 0xFFFF0000u) : __uint_as_float(c << 16);
        sum += odd ? __uint_as_float(d & 0xFFFF0000u) : __uint_as_float(d << 16);
    }
    for (; i < hi; i++) {
        unsigned a = g_bufBh[(size_t)i * 64 + w2];
        sum += odd ? __uint_as_float(a & 0xFFFF0000u) : __uint_as_float(a << 16);
    }
    if (lo < hi) atomicAdd(&g_pool[g * 128 + col], sum);
}

// ---------------- MLP head (+ pool cleanup for next run) ------------------------
__global__ void k_mlp(const float* __restrict__ Wo1, const float* __restrict__ bo1,
                      const float* __restrict__ Wo2, const float* __restrict__ bo2,
                      float* __restrict__ out) {
    __shared__ float ps[128];
    __shared__ float zs[64];
    int g = blockIdx.x;
    int t = threadIdx.x;
    int cnt = g_goff[g + 1] - g_goff[g];
    float inv = 1.0f / fmaxf((float)cnt, 1.0f);
    ps[t]      = g_pool[g * 128 + t] * inv;
    ps[t + 64] = g_pool[g * 128 + t + 64] * inv;
    g_pool[g * 128 + t] = 0.f;          // self-clean for next run
    g_pool[g * 128 + t + 64] = 0.f;
    __syncthreads();
    float z = bo1[t];
#pragma unroll 8
    for (int k = 0; k < 128; k++) z = fmaf(ps[k], Wo1[k * 64 + t], z);
    zs[t] = fmaxf(z, 0.f);
    __syncthreads();
    if (t < OUTD) {
        float o = bo2[t];
#pragma unroll 8
        for (int j = 0; j < 64; j++) o = fmaf(zs[j], Wo2[j * 32 + t], o);
        out[g * OUTD + t] = o;
    }
}

// ---------------- launch ------------------------------------------------------------
extern "C" void kernel_launch(void* const* d_in, const int* in_sizes, int n_in,
                              void* d_out, int out_size) {
    const float* x    = (const float*)d_in[0];
    const int*   ei   = (const int*)d_in[1];
    const int*   batch= (const int*)d_in[2];
    const float* W1   = (const float*)d_in[3];
    const float* b1   = (const float*)d_in[4];
    const float* W2   = (const float*)d_in[5];
    const float* b2   = (const float*)d_in[6];
    const float* W3   = (const float*)d_in[7];
    const float* b3   = (const float*)d_in[8];
    const float* Wo1  = (const float*)d_in[9];
    const float* bo1  = (const float*)d_in[10];
    const float* Wo2  = (const float*)d_in[11];
    const float* bo2  = (const float*)d_in[12];
    float* out = (float*)d_out;

    cudaFuncSetAttribute(k_gemm_mma, cudaFuncAttributeMaxDynamicSharedMemorySize, GSM);

    const int PREP_TASKS = NN * 32 + 3 * 2048;
    const int GEMM_BLOCKS = (NN + 127) / 128;
    const int AGG_BLOCKS  = (NN + 7) / 8;

    k_prep<<<(PREP_TASKS + 255) / 256, 256>>>(x, ei, batch, W1, W2, W3);  // 0
    k_scan<<<SCAN_PARTS, SCAN_CHUNK>>>();                                 // 1
    k_fill<<<(EE + NN + 255) / 256, 256>>>(ei);                           // 2
    k_agg<<<AGG_BLOCKS, 256>>>();                                         // 3 <- ncu slot
    k_gemm_mma<<<GEMM_BLOCKS, 256, GSM>>>(0, b1, 0);                      // 4
    k_agg<<<AGG_BLOCKS, 256>>>();                                         // 5
    k_gemm_mma<<<GEMM_BLOCKS, 256, GSM>>>(1, b2, 0);                      // 6
    k_agg<<<AGG_BLOCKS, 256>>>();                                         // 7
    k_gemm_mma<<<GEMM_BLOCKS, 256, GSM>>>(2, b3, 1);                      // 8
    k_pool<<<GG * 8, 128>>>();                                            // 9
    k_mlp<<<GG, 64>>>(Wo1, bo1, Wo2, bo2, out);                           // 10
}